// round 7
// baseline (speedup 1.0000x reference)
#include <cuda_runtime.h>
#include <cuda_bf16.h>
#include <cstdint>

#define DINL __device__ __forceinline__

// ---------------- smem layout (bytes) ----------------
constexpr int SM_BIAS = 0;            // 800 floats (b1|b2|b3|b4)
constexpr int SM_W2   = 3200;         // 32 rows x RS576
constexpr int SM_W3   = 21632;        // 128 rows x RS192
constexpr int SM_A    = 46208;        // 2 x 40960 double buffer (W1 chunks / W4 chunks)
constexpr int SM_BUFS = 40960;
constexpr int SM_EX   = SM_A + 2 * SM_BUFS;   // 128128: exchange region
// z2 partials: 2 halves x 128 rows x 136B = 34816 ; d-frags: 128 x 576 = 73728
constexpr int EX_HALF = 17408;
constexpr int SM_TOTAL= SM_EX + 73728;        // 201856

// ---------------- preconverted weight fragments (global scratch) ----------------
__device__ __align__(256) unsigned char gW1[8 * 128 * 256];
__device__ __align__(256) unsigned char gW2[32 * 512];
__device__ __align__(256) unsigned char gW3[128 * 128];
__device__ __align__(256) unsigned char gW4[512 * 512];

DINL void mma16816(float c[4], uint32_t a0, uint32_t a1, uint32_t a2, uint32_t a3,
                   uint32_t b0, uint32_t b1) {
    asm volatile("mma.sync.aligned.m16n8k16.row.col.f32.bf16.bf16.f32 "
        "{%0,%1,%2,%3}, {%4,%5,%6,%7}, {%8,%9}, {%0,%1,%2,%3};"
        : "+f"(c[0]), "+f"(c[1]), "+f"(c[2]), "+f"(c[3])
        : "r"(a0), "r"(a1), "r"(a2), "r"(a3), "r"(b0), "r"(b1));
}

DINL void split2(float a, float b, uint32_t& h, uint32_t& l) {
    __nv_bfloat16 ha = __float2bfloat16(a), hb = __float2bfloat16(b);
    __nv_bfloat16 la = __float2bfloat16(a - __bfloat162float(ha));
    __nv_bfloat16 lb = __float2bfloat16(b - __bfloat162float(hb));
    h = ((uint32_t)__bfloat16_as_ushort(hb) << 16) | (uint32_t)__bfloat16_as_ushort(ha);
    l = ((uint32_t)__bfloat16_as_ushort(lb) << 16) | (uint32_t)__bfloat16_as_ushort(la);
}

// write one 4-k group of a fragment row: 16B slot = {h0, l0@+8, h1@+16, l1@+24}? No:
// slot layout: {h(k), h(k+8)} at +0/+4? -> matches reader: uint4 {h0, h1, l0, l1}
DINL void frag_store(unsigned char* p, float4 v) {
    uint32_t h0, l0, h1, l1;
    split2(v.x, v.y, h0, l0);
    split2(v.z, v.w, h1, l1);
    *(uint32_t*)(p)      = h0;
    *(uint32_t*)(p + 8)  = l0;
    *(uint32_t*)(p + 16) = h1;
    *(uint32_t*)(p + 24) = l1;
}

// ---------------- setup kernel: convert weights to fragment layout ----------------
__global__ void __launch_bounds__(256) setup_kernel(
    const float* __restrict__ W1, const float* __restrict__ W2,
    const float* __restrict__ W3, const float* __restrict__ W4)
{
    int i = blockIdx.x * 256 + threadIdx.x;
    if (i < 16384) {                       // W1 [128 x 512], chunk-major dst
        int r = i >> 7, k = (i & 127) << 2;
        float4 v = __ldg((const float4*)(W1 + (size_t)r * 512 + k));
        int c = k >> 6, kb = (k >> 4) & 3, q = (k & 7) >> 1, sub = ((k >> 3) & 1) << 2;
        frag_store(gW1 + c * 32768 + r * 256 + kb * 64 + q * 16 + sub, v);
    } else if (i < 32768) {                // W4 [512 x 128]
        int j = i - 16384;
        int r = j >> 5, k = (j & 31) << 2;
        float4 v = __ldg((const float4*)(W4 + (size_t)r * 128 + k));
        int kb = k >> 4, q = (k & 7) >> 1, sub = ((k >> 3) & 1) << 2;
        frag_store(gW4 + r * 512 + kb * 64 + q * 16 + sub, v);
    } else if (i < 33792) {                // W2 [32 x 128]
        int j = i - 32768;
        int r = j >> 5, k = (j & 31) << 2;
        float4 v = __ldg((const float4*)(W2 + (size_t)r * 128 + k));
        int kb = k >> 4, q = (k & 7) >> 1, sub = ((k >> 3) & 1) << 2;
        frag_store(gW2 + r * 512 + kb * 64 + q * 16 + sub, v);
    } else if (i < 34816) {                // W3 [128 x 32]
        int j = i - 33792;
        int r = j >> 3, k = (j & 7) << 2;
        float4 v = __ldg((const float4*)(W3 + (size_t)r * 32 + k));
        int kb = k >> 4, q = (k & 7) >> 1, sub = ((k >> 3) & 1) << 2;
        frag_store(gW3 + r * 128 + kb * 64 + q * 16 + sub, v);
    }
}

// ---------------- cp.async helpers ----------------
DINL void cpa16(uint32_t sdst, const void* gsrc) {
    asm volatile("cp.async.cg.shared.global [%0], [%1], 16;"
                 :: "r"(sdst), "l"(gsrc) : "memory");
}
#define CPCOMMIT() asm volatile("cp.async.commit_group;" ::: "memory")
#define CPWAIT1()  asm volatile("cp.async.wait_group 1;" ::: "memory")
#define CPWAIT0()  asm volatile("cp.async.wait_group 0;" ::: "memory")

DINL uint32_t smem_u32(const void* p) {
    uint32_t a;
    asm("{ .reg .u64 t; cvta.to.shared.u64 t, %1; cvt.u32.u64 %0, t; }" : "=r"(a) : "l"(p));
    return a;
}

template<int ROWS, int IPR, int RSD>
DINL void cppad(uint32_t sdst, const unsigned char* __restrict__ gsrc, int t) {
    constexpr int TOT = ROWS * IPR;
    #pragma unroll
    for (int i = t; i < TOT; i += 256) {
        int r = i / IPR, ii = i - r * IPR;
        cpa16(sdst + r * RSD + ii * 16, gsrc + (size_t)i * 16);
    }
}

// per-chunk x fragments for 2 m-tiles (hi/lo split at load time) — 64 regs
struct XFrag { uint32_t h[4][2][4]; uint32_t l[4][2][4]; };

DINL void loadx_split(const float* __restrict__ xr, int c, XFrag& f, int q) {
    #pragma unroll
    for (int kb = 0; kb < 4; kb++) {
        #pragma unroll
        for (int mt = 0; mt < 2; mt++) {
            const float* p = xr + mt * 16 * 512;
            int k0 = c * 64 + kb * 16 + q * 2;
            float2 v0 = __ldg((const float2*)(p + k0));
            float2 v1 = __ldg((const float2*)(p + 8 * 512 + k0));
            float2 v2 = __ldg((const float2*)(p + k0 + 8));
            float2 v3 = __ldg((const float2*)(p + 8 * 512 + k0 + 8));
            split2(v0.x, v0.y, f.h[kb][mt][0], f.l[kb][mt][0]);
            split2(v1.x, v1.y, f.h[kb][mt][1], f.l[kb][mt][1]);
            split2(v2.x, v2.y, f.h[kb][mt][2], f.l[kb][mt][2]);
            split2(v3.x, v3.y, f.h[kb][mt][3], f.l[kb][mt][3]);
        }
    }
}

// GEMM1 chunk: 4 kb x 8 j x 2 mt x 3 passes; one B LDS.128 feeds 6 HMMAs
DINL void compute_chunk1(const char* smc, int buf, const XFrag& f,
                         int bn, int q, float acc[2][8][4]) {
    #pragma unroll
    for (int kb = 0; kb < 4; kb++) {
        #pragma unroll
        for (int j = 0; j < 8; j++) {
            uint4 vb = *(const uint4*)(smc + buf + (size_t)(bn + j * 8) * 320 + kb * 64 + q * 16);
            #pragma unroll
            for (int mt = 0; mt < 2; mt++) {
                mma16816(acc[mt][j], f.h[kb][mt][0], f.h[kb][mt][1], f.h[kb][mt][2], f.h[kb][mt][3], vb.x, vb.y);
                mma16816(acc[mt][j], f.h[kb][mt][0], f.h[kb][mt][1], f.h[kb][mt][2], f.h[kb][mt][3], vb.z, vb.w);
                mma16816(acc[mt][j], f.l[kb][mt][0], f.l[kb][mt][1], f.l[kb][mt][2], f.l[kb][mt][3], vb.x, vb.y);
            }
        }
    }
}

__global__ void __launch_bounds__(256, 1) channel_net_kernel(
    const float* __restrict__ x, const float* __restrict__ noise, const float* __restrict__ hch,
    const float* __restrict__ b1, const float* __restrict__ b2,
    const float* __restrict__ b3, const float* __restrict__ b4,
    float* __restrict__ out)
{
    extern __shared__ char smc[];
    const uint32_t sb = smem_u32(smc);
    const int t = threadIdx.x;
    const int w = t >> 5, lane = t & 31, g = lane >> 2, q = lane & 3;
    const int wm = w & 3, wn = w >> 2;       // 4 M-groups x 2 N-halves
    const int row0 = blockIdx.x * 128;
    float* bias = (float*)(smc + SM_BIAS);

    for (int i = t; i < 128; i += 256) bias[i]       = __ldg(b1 + i);
    for (int i = t; i < 32;  i += 256) bias[128 + i] = __ldg(b2 + i);
    for (int i = t; i < 128; i += 256) bias[160 + i] = __ldg(b3 + i);
    for (int i = t; i < 512; i += 256) bias[288 + i] = __ldg(b4 + i);

    // prologue: W2 + W3 + W1 chunk0 -> group0 ; W1 chunk1 -> group1
    cppad<32, 32, 576>(sb + SM_W2, gW2, t);
    cppad<128, 8, 192>(sb + SM_W3, gW3, t);
    cppad<128, 16, 320>(sb + SM_A, gW1, t);
    CPCOMMIT();
    cppad<128, 16, 320>(sb + SM_A + SM_BUFS, gW1 + 32768, t);
    CPCOMMIT();

    const float* xrow = x + (size_t)(row0 + 32 * wm + g) * 512;
    const int bn1 = 64 * wn + g;             // GEMM1/W1 B row base
    XFrag xfA, xfB;
    loadx_split(xrow, 0, xfA, q);

    float acc[2][8][4];
    #pragma unroll
    for (int mt = 0; mt < 2; mt++)
        #pragma unroll
        for (int j = 0; j < 8; j++)
            { acc[mt][j][0]=0.f; acc[mt][j][1]=0.f; acc[mt][j][2]=0.f; acc[mt][j][3]=0.f; }

    // ============== GEMM1: z1[128x128] = x @ W1^T, 8 chunks of 64 k ==============
    for (int c = 0; c < 8; c += 2) {
        loadx_split(xrow, c + 1, xfB, q);
        CPWAIT1(); __syncthreads();
        compute_chunk1(smc, SM_A, xfA, bn1, q, acc);
        __syncthreads();
        if (c + 2 < 8) { cppad<128, 16, 320>(sb + SM_A, gW1 + (size_t)(c + 2) * 32768, t); CPCOMMIT(); }
        if (c + 2 < 8) loadx_split(xrow, c + 2, xfA, q);
        if (c == 6) { CPWAIT0(); } else { CPWAIT1(); }
        __syncthreads();
        compute_chunk1(smc, SM_A + SM_BUFS, xfB, bn1, q, acc);
        __syncthreads();
        if (c + 3 < 8) { cppad<128, 16, 320>(sb + SM_A + SM_BUFS, gW1 + (size_t)(c + 3) * 32768, t); CPCOMMIT(); }
    }

    // kick off W4 chunk 0/1 copies — overlap with GEMM2/3 and exchanges
    cppad<64, 32, 576>(sb + SM_A, gW4, t);
    CPCOMMIT();
    cppad<64, 32, 576>(sb + SM_A + SM_BUFS, gW4 + 64 * 512, t);
    CPCOMMIT();

    // ---- epilogue 1: +b1, relu, split -> A2 fragments (rows 32wm..+32, k half 64wn..) ----
    uint32_t a2h[4][2][4], a2l[4][2][4];
    #pragma unroll
    for (int mt = 0; mt < 2; mt++) {
        #pragma unroll
        for (int j = 0; j < 8; j++) {
            int col = 64 * wn + j * 8 + q * 2;
            float bb0 = bias[col], bb1 = bias[col + 1];
            float v0 = fmaxf(acc[mt][j][0] + bb0, 0.f), v1 = fmaxf(acc[mt][j][1] + bb1, 0.f);
            float v2 = fmaxf(acc[mt][j][2] + bb0, 0.f), v3 = fmaxf(acc[mt][j][3] + bb1, 0.f);
            uint32_t h01, l01, h23, l23;
            split2(v0, v1, h01, l01);
            split2(v2, v3, h23, l23);
            int kb = j >> 1, s = (j & 1) * 2;
            a2h[kb][mt][s] = h01; a2h[kb][mt][s + 1] = h23;
            a2l[kb][mt][s] = l01; a2l[kb][mt][s + 1] = l23;
        }
    }

    // ============== GEMM2 (split-K): partial z2 over k in [64wn, 64wn+64) ==============
    float acc2[2][4][4];
    #pragma unroll
    for (int mt = 0; mt < 2; mt++)
        #pragma unroll
        for (int j = 0; j < 4; j++)
            { acc2[mt][j][0]=0.f; acc2[mt][j][1]=0.f; acc2[mt][j][2]=0.f; acc2[mt][j][3]=0.f; }
    #pragma unroll
    for (int kb = 0; kb < 4; kb++) {
        int kbg = 4 * wn + kb;
        #pragma unroll
        for (int j = 0; j < 4; j++) {
            uint4 vb = *(const uint4*)(smc + SM_W2 + (size_t)(j * 8 + g) * 576 + kbg * 64 + q * 16);
            #pragma unroll
            for (int mt = 0; mt < 2; mt++) {
                mma16816(acc2[mt][j], a2h[kb][mt][0], a2h[kb][mt][1], a2h[kb][mt][2], a2h[kb][mt][3], vb.x, vb.y);
                mma16816(acc2[mt][j], a2h[kb][mt][0], a2h[kb][mt][1], a2h[kb][mt][2], a2h[kb][mt][3], vb.z, vb.w);
                mma16816(acc2[mt][j], a2l[kb][mt][0], a2l[kb][mt][1], a2l[kb][mt][2], a2l[kb][mt][3], vb.x, vb.y);
            }
        }
    }

    // write partials: part[wn][row][col] fp32, row stride 136
    {
        char* p = smc + SM_EX + wn * EX_HALF;
        #pragma unroll
        for (int mt = 0; mt < 2; mt++) {
            #pragma unroll
            for (int j = 0; j < 4; j++) {
                int r = 32 * wm + 16 * mt + g;
                int c0 = j * 8 + q * 2;
                *(float2*)(p + (size_t)r * 136 + c0 * 4)       = make_float2(acc2[mt][j][0], acc2[mt][j][1]);
                *(float2*)(p + (size_t)(r + 8) * 136 + c0 * 4) = make_float2(acc2[mt][j][2], acc2[mt][j][3]);
            }
        }
    }
    __syncthreads();

    // ---- epilogue 2 (owner rows 16w..16w+16): reduce, +b2, normalize, rotate, +noise ----
    uint32_t a3h[2][4], a3l[2][4];
    {
        const char* p0 = smc + SM_EX;
        const char* p1 = smc + SM_EX + EX_HALF;
        int r = 16 * w + g;
        float vv[4][4];
        float ssg = 0.f, ssh = 0.f;
        #pragma unroll
        for (int j = 0; j < 4; j++) {
            int c0 = j * 8 + q * 2;
            float2 u0a = *(const float2*)(p0 + (size_t)r * 136 + c0 * 4);
            float2 u1a = *(const float2*)(p1 + (size_t)r * 136 + c0 * 4);
            float2 u0b = *(const float2*)(p0 + (size_t)(r + 8) * 136 + c0 * 4);
            float2 u1b = *(const float2*)(p1 + (size_t)(r + 8) * 136 + c0 * 4);
            float bb0 = bias[128 + c0], bb1 = bias[128 + c0 + 1];
            vv[j][0] = u0a.x + u1a.x + bb0; vv[j][1] = u0a.y + u1a.y + bb1;
            vv[j][2] = u0b.x + u1b.x + bb0; vv[j][3] = u0b.y + u1b.y + bb1;
            ssg += vv[j][0] * vv[j][0] + vv[j][1] * vv[j][1];
            ssh += vv[j][2] * vv[j][2] + vv[j][3] * vv[j][3];
        }
        ssg += __shfl_xor_sync(0xffffffffu, ssg, 1);
        ssg += __shfl_xor_sync(0xffffffffu, ssg, 2);
        ssh += __shfl_xor_sync(0xffffffffu, ssh, 1);
        ssh += __shfl_xor_sync(0xffffffffu, ssh, 2);
        float scg = 4.0f / sqrtf(ssg);       // sqrt(N*0.5) = 4
        float sch = 4.0f / sqrtf(ssh);
        float hc = __ldg(hch), hs = __ldg(hch + 1);
        int rg = row0 + 16 * w + g;
        #pragma unroll
        for (int j = 0; j < 4; j++) {
            float2 ng = __ldg((const float2*)(noise + (size_t)rg * 32 + j * 8 + q * 2));
            float2 nh = __ldg((const float2*)(noise + (size_t)(rg + 8) * 32 + j * 8 + q * 2));
            float y0 = scg * (vv[j][0] * hc - vv[j][1] * hs) + ng.x;
            float y1 = scg * (vv[j][0] * hs + vv[j][1] * hc) + ng.y;
            float y2 = sch * (vv[j][2] * hc - vv[j][3] * hs) + nh.x;
            float y3 = sch * (vv[j][2] * hs + vv[j][3] * hc) + nh.y;
            uint32_t h01, l01, h23, l23;
            split2(y0, y1, h01, l01);
            split2(y2, y3, h23, l23);
            int kb = j >> 1, s = (j & 1) * 2;
            a3h[kb][s] = h01; a3h[kb][s + 1] = h23;
            a3l[kb][s] = l01; a3l[kb][s + 1] = l23;
        }
    }

    // ============== GEMM3: d[rows 16w..+16][128] = y @ W3^T (K=32) ==============
    float acc3[16][4];
    #pragma unroll
    for (int j = 0; j < 16; j++) { acc3[j][0]=0.f; acc3[j][1]=0.f; acc3[j][2]=0.f; acc3[j][3]=0.f; }
    #pragma unroll
    for (int kb = 0; kb < 2; kb++) {
        #pragma unroll
        for (int j = 0; j < 16; j++) {
            uint4 vb = *(const uint4*)(smc + SM_W3 + (size_t)(j * 8 + g) * 192 + kb * 64 + q * 16);
            mma16816(acc3[j], a3h[kb][0], a3h[kb][1], a3h[kb][2], a3h[kb][3], vb.x, vb.y);
            mma16816(acc3[j], a3h[kb][0], a3h[kb][1], a3h[kb][2], a3h[kb][3], vb.z, vb.w);
            mma16816(acc3[j], a3l[kb][0], a3l[kb][1], a3l[kb][2], a3l[kb][3], vb.x, vb.y);
        }
    }

    // ---- epilogue 3: +b3, relu, split; exchange d through smem in frag layout ----
    __syncthreads();     // partial region no longer read; reuse SM_EX for d-frags
    {
        char* p = smc + SM_EX;
        int r0 = 16 * w + g;
        #pragma unroll
        for (int j = 0; j < 16; j++) {
            int col = j * 8 + q * 2;
            float bb0 = bias[160 + col], bb1 = bias[160 + col + 1];
            float v0 = fmaxf(acc3[j][0] + bb0, 0.f), v1 = fmaxf(acc3[j][1] + bb1, 0.f);
            float v2 = fmaxf(acc3[j][2] + bb0, 0.f), v3 = fmaxf(acc3[j][3] + bb1, 0.f);
            uint32_t h01, l01, h23, l23;
            split2(v0, v1, h01, l01);
            split2(v2, v3, h23, l23);
            int off = (j >> 1) * 64 + q * 16 + (j & 1) * 4;
            *(uint32_t*)(p + (size_t)r0 * 576 + off)           = h01;
            *(uint32_t*)(p + (size_t)r0 * 576 + off + 8)       = l01;
            *(uint32_t*)(p + (size_t)(r0 + 8) * 576 + off)     = h23;
            *(uint32_t*)(p + (size_t)(r0 + 8) * 576 + off + 8) = l23;
        }
    }
    __syncthreads();

    // read A4 fragments: rows 32wm..+32, all 8 kb (128 regs, reused for 8 chunks)
    uint32_t a4h[8][2][4], a4l[8][2][4];
    #pragma unroll
    for (int kb = 0; kb < 8; kb++) {
        #pragma unroll
        for (int mt = 0; mt < 2; mt++) {
            int r = 32 * wm + 16 * mt + g;
            uint4 va0 = *(const uint4*)(smc + SM_EX + (size_t)r * 576 + kb * 64 + q * 16);
            uint4 va1 = *(const uint4*)(smc + SM_EX + (size_t)(r + 8) * 576 + kb * 64 + q * 16);
            a4h[kb][mt][0] = va0.x; a4h[kb][mt][1] = va1.x;
            a4h[kb][mt][2] = va0.y; a4h[kb][mt][3] = va1.y;
            a4l[kb][mt][0] = va0.z; a4l[kb][mt][1] = va1.z;
            a4l[kb][mt][2] = va0.w; a4l[kb][mt][3] = va1.w;
        }
    }

    // ============== GEMM4: out[128x512] = d @ W4^T, 8 n-chunks of 64 ==============
    const int bn4 = 32 * wn + g;
    for (int nc = 0; nc < 8; nc++) {
        if (nc == 7) { CPWAIT0(); } else { CPWAIT1(); }
        __syncthreads();
        int buf = SM_A + (nc & 1) * SM_BUFS;
        float acc4[2][4][4];
        #pragma unroll
        for (int mt = 0; mt < 2; mt++)
            #pragma unroll
            for (int j = 0; j < 4; j++)
                { acc4[mt][j][0]=0.f; acc4[mt][j][1]=0.f; acc4[mt][j][2]=0.f; acc4[mt][j][3]=0.f; }
        #pragma unroll
        for (int kb = 0; kb < 8; kb++) {
            #pragma unroll
            for (int j = 0; j < 4; j++) {
                uint4 vb = *(const uint4*)(smc + buf + (size_t)(bn4 + j * 8) * 576 + kb * 64 + q * 16);
                #pragma unroll
                for (int mt = 0; mt < 2; mt++) {
                    mma16816(acc4[mt][j], a4h[kb][mt][0], a4h[kb][mt][1], a4h[kb][mt][2], a4h[kb][mt][3], vb.x, vb.y);
                    mma16816(acc4[mt][j], a4h[kb][mt][0], a4h[kb][mt][1], a4h[kb][mt][2], a4h[kb][mt][3], vb.z, vb.w);
                    mma16816(acc4[mt][j], a4l[kb][mt][0], a4l[kb][mt][1], a4l[kb][mt][2], a4l[kb][mt][3], vb.x, vb.y);
                }
            }
        }
        __syncthreads();
        if (nc + 2 < 8) {
            cppad<64, 32, 576>(sb + buf, gW4 + (size_t)(nc + 2) * 64 * 512, t);
            CPCOMMIT();
        }
        // epilogue 4: +b4, store fp32
        #pragma unroll
        for (int mt = 0; mt < 2; mt++) {
            #pragma unroll
            for (int j = 0; j < 4; j++) {
                int col = nc * 64 + 32 * wn + j * 8 + q * 2;
                float bb0 = bias[288 + col], bb1 = bias[288 + col + 1];
                int r = row0 + 32 * wm + 16 * mt + g;
                *(float2*)(out + (size_t)r * 512 + col) =
                    make_float2(acc4[mt][j][0] + bb0, acc4[mt][j][1] + bb1);
                *(float2*)(out + (size_t)(r + 8) * 512 + col) =
                    make_float2(acc4[mt][j][2] + bb0, acc4[mt][j][3] + bb1);
            }
        }
    }
}

extern "C" void kernel_launch(void* const* d_in, const int* in_sizes, int n_in,
                              void* d_out, int out_size) {
    const float* x     = (const float*)d_in[0];
    const float* noise = (const float*)d_in[1];
    const float* hch   = (const float*)d_in[2];
    const float* W1    = (const float*)d_in[3];
    const float* b1    = (const float*)d_in[4];
    const float* W2    = (const float*)d_in[5];
    const float* b2    = (const float*)d_in[6];
    const float* W3    = (const float*)d_in[7];
    const float* b3    = (const float*)d_in[8];
    const float* W4    = (const float*)d_in[9];
    const float* b4    = (const float*)d_in[10];
    float* out = (float*)d_out;

    static int configured = 0;
    if (!configured) {
        cudaFuncSetAttribute(channel_net_kernel,
                             cudaFuncAttributeMaxDynamicSharedMemorySize, SM_TOTAL);
        configured = 1;
    }
    setup_kernel<<<136, 256>>>(W1, W2, W3, W4);
    channel_net_kernel<<<1024, 256, SM_TOTAL>>>(
        x, noise, hch, b1, b2, b3, b4, out);
}

// round 8
// speedup vs baseline: 1.3637x; 1.3637x over previous
#include <cuda_runtime.h>
#include <cuda_bf16.h>
#include <cstdint>

#define DINL __device__ __forceinline__

// ---------------- smem layout (bytes), per 128-thread CTA ----------------
constexpr int SM_BIAS  = 0;            // 800 floats (b1|b2|b3|b4)
constexpr int SM_W2    = 3200;         // 32 rows x stride 576 (512B data)
constexpr int SM_W3    = 21632;        // 128 rows x stride 192 (128B data)
constexpr int SM_NOISE = 46208;        // 64 rows x stride 144 (128B data)
constexpr int SM_BUF   = 55424;        // 2 x 24576 double buffer
constexpr int SM_BUFS  = 24576;        // holds W1 chunk (128r x 192) or W4 chunk (32r x 576)
constexpr int SM_TOTAL = SM_BUF + 2 * SM_BUFS;   // 104576 (~102KB -> 2 CTAs/SM)

// ---------------- preconverted weight fragments (global scratch) ----------------
// W1: chunk-major [16 chunks of 32k][128 rows][128B]
// W4: row-major [512 rows][512B]; W2: [32][512B]; W3: [128][128B]
__device__ __align__(256) unsigned char gW1[16 * 128 * 128];
__device__ __align__(256) unsigned char gW2[32 * 512];
__device__ __align__(256) unsigned char gW3[128 * 128];
__device__ __align__(256) unsigned char gW4[512 * 512];

DINL void mma16816(float c[4], uint32_t a0, uint32_t a1, uint32_t a2, uint32_t a3,
                   uint32_t b0, uint32_t b1) {
    asm volatile("mma.sync.aligned.m16n8k16.row.col.f32.bf16.bf16.f32 "
        "{%0,%1,%2,%3}, {%4,%5,%6,%7}, {%8,%9}, {%0,%1,%2,%3};"
        : "+f"(c[0]), "+f"(c[1]), "+f"(c[2]), "+f"(c[3])
        : "r"(a0), "r"(a1), "r"(a2), "r"(a3), "r"(b0), "r"(b1));
}

DINL void split2(float a, float b, uint32_t& h, uint32_t& l) {
    __nv_bfloat16 ha = __float2bfloat16(a), hb = __float2bfloat16(b);
    __nv_bfloat16 la = __float2bfloat16(a - __bfloat162float(ha));
    __nv_bfloat16 lb = __float2bfloat16(b - __bfloat162float(hb));
    h = ((uint32_t)__bfloat16_as_ushort(hb) << 16) | (uint32_t)__bfloat16_as_ushort(ha);
    l = ((uint32_t)__bfloat16_as_ushort(lb) << 16) | (uint32_t)__bfloat16_as_ushort(la);
}

// 16B frag slot: {h(k,k+1)} @+0, {l(k,k+1)} @+8; k+2,k+3 at +16/+24
DINL void frag_store(unsigned char* p, float4 v) {
    uint32_t h0, l0, h1, l1;
    split2(v.x, v.y, h0, l0);
    split2(v.z, v.w, h1, l1);
    *(uint32_t*)(p)      = h0;
    *(uint32_t*)(p + 8)  = l0;
    *(uint32_t*)(p + 16) = h1;
    *(uint32_t*)(p + 24) = l1;
}

// ---------------- setup kernel: convert weights to fragment layout ----------------
__global__ void __launch_bounds__(256) setup_kernel(
    const float* __restrict__ W1, const float* __restrict__ W2,
    const float* __restrict__ W3, const float* __restrict__ W4)
{
    int i = blockIdx.x * 256 + threadIdx.x;
    if (i < 16384) {                       // W1 [128 x 512], 32k-chunk-major dst
        int r = i >> 7, k = (i & 127) << 2;
        float4 v = __ldg((const float4*)(W1 + (size_t)r * 512 + k));
        int c = k >> 5, kb = (k >> 4) & 1, q = (k & 7) >> 1, sub = ((k >> 3) & 1) << 2;
        frag_store(gW1 + c * 16384 + r * 128 + kb * 64 + q * 16 + sub, v);
    } else if (i < 32768) {                // W4 [512 x 128]
        int j = i - 16384;
        int r = j >> 5, k = (j & 31) << 2;
        float4 v = __ldg((const float4*)(W4 + (size_t)r * 128 + k));
        int kb = k >> 4, q = (k & 7) >> 1, sub = ((k >> 3) & 1) << 2;
        frag_store(gW4 + r * 512 + kb * 64 + q * 16 + sub, v);
    } else if (i < 33792) {                // W2 [32 x 128]
        int j = i - 32768;
        int r = j >> 5, k = (j & 31) << 2;
        float4 v = __ldg((const float4*)(W2 + (size_t)r * 128 + k));
        int kb = k >> 4, q = (k & 7) >> 1, sub = ((k >> 3) & 1) << 2;
        frag_store(gW2 + r * 512 + kb * 64 + q * 16 + sub, v);
    } else if (i < 34816) {                // W3 [128 x 32]
        int j = i - 33792;
        int r = j >> 3, k = (j & 7) << 2;
        float4 v = __ldg((const float4*)(W3 + (size_t)r * 32 + k));
        int kb = k >> 4, q = (k & 7) >> 1, sub = ((k >> 3) & 1) << 2;
        frag_store(gW3 + r * 128 + kb * 64 + q * 16 + sub, v);
    }
}

// ---------------- cp.async helpers ----------------
DINL void cpa16(uint32_t sdst, const void* gsrc) {
    asm volatile("cp.async.cg.shared.global [%0], [%1], 16;"
                 :: "r"(sdst), "l"(gsrc) : "memory");
}
#define CPCOMMIT() asm volatile("cp.async.commit_group;" ::: "memory")
#define CPWAIT1()  asm volatile("cp.async.wait_group 1;" ::: "memory")
#define CPWAIT0()  asm volatile("cp.async.wait_group 0;" ::: "memory")

DINL uint32_t smem_u32(const void* p) {
    uint32_t a;
    asm("{ .reg .u64 t; cvta.to.shared.u64 t, %1; cvt.u32.u64 %0, t; }" : "=r"(a) : "l"(p));
    return a;
}

// copy ROWS x (IPR*16B) contiguous gmem -> smem with padded row stride RSD (128 threads)
template<int ROWS, int IPR, int RSD>
DINL void cppad(uint32_t sdst, const unsigned char* __restrict__ gsrc, int t) {
    constexpr int TOT = ROWS * IPR;
    #pragma unroll
    for (int i = t; i < TOT; i += 128) {
        int r = i / IPR, ii = i - r * IPR;
        cpa16(sdst + r * RSD + ii * 16, gsrc + (size_t)i * 16);
    }
}

// one 16-k step, A from registers, B from smem (stride RSB), NJ n-tiles, 3-pass split
template<int NJ, int RSB>
DINL void gemm_step_r(const char* smc, const uint32_t ah[4], const uint32_t al[4],
                      int boff, int g, int q, float (*acc)[4]) {
    #pragma unroll
    for (int j = 0; j < NJ; j++) {
        uint4 vb = *(const uint4*)(smc + boff + (size_t)(j * 8 + g) * RSB + q * 16);
        mma16816(acc[j], ah[0], ah[1], ah[2], ah[3], vb.x, vb.y);
        mma16816(acc[j], ah[0], ah[1], ah[2], ah[3], vb.z, vb.w);
        mma16816(acc[j], al[0], al[1], al[2], al[3], vb.x, vb.y);
    }
}

// prefetch x fp32 fragments for one 32-k chunk (8 float2 = 16 regs)
DINL void loadx(const float* __restrict__ xrow, int c, float2 xf[8], int q) {
    const float* p0 = xrow;              // row g
    const float* p1 = xrow + 8 * 512;    // row g+8
    #pragma unroll
    for (int kb = 0; kb < 2; kb++) {
        int k0 = c * 32 + kb * 16 + q * 2;
        xf[kb * 4 + 0] = __ldg((const float2*)(p0 + k0));
        xf[kb * 4 + 1] = __ldg((const float2*)(p1 + k0));
        xf[kb * 4 + 2] = __ldg((const float2*)(p0 + k0 + 8));
        xf[kb * 4 + 3] = __ldg((const float2*)(p1 + k0 + 8));
    }
}

// GEMM1 chunk compute: 2 kb x 16 j, A converted inline from xf
DINL void compute_chunk1(const char* smc, int buf, const float2 xf[8],
                         int g, int q, float (*acc)[4]) {
    #pragma unroll
    for (int kb = 0; kb < 2; kb++) {
        uint32_t ah[4], al[4];
        #pragma unroll
        for (int s = 0; s < 4; s++)
            split2(xf[kb * 4 + s].x, xf[kb * 4 + s].y, ah[s], al[s]);
        gemm_step_r<16, 192>(smc, ah, al, buf + kb * 64, g, q, acc);
    }
}

__global__ void __launch_bounds__(128, 2) channel_net_kernel(
    const float* __restrict__ x, const float* __restrict__ noise, const float* __restrict__ hch,
    const float* __restrict__ b1, const float* __restrict__ b2,
    const float* __restrict__ b3, const float* __restrict__ b4,
    float* __restrict__ out)
{
    extern __shared__ char smc[];
    const uint32_t sb = smem_u32(smc);
    const int t = threadIdx.x;
    const int w = t >> 5, lane = t & 31, g = lane >> 2, q = lane & 3;
    const int row0 = blockIdx.x * 64;          // 64 rows per CTA, 4 warps x 16 rows
    float* bias = (float*)(smc + SM_BIAS);

    for (int i = t; i < 128; i += 128) bias[i]       = __ldg(b1 + i);
    if (t < 32)                        bias[128 + t] = __ldg(b2 + t);
    for (int i = t; i < 128; i += 128) bias[160 + i] = __ldg(b3 + i);
    for (int i = t; i < 512; i += 128) bias[288 + i] = __ldg(b4 + i);

    // prologue group0: W2 + W3 + noise + W1 chunk0 ; group1: W1 chunk1
    cppad<32, 32, 576>(sb + SM_W2, gW2, t);
    cppad<128, 8, 192>(sb + SM_W3, gW3, t);
    cppad<64, 8, 144>(sb + SM_NOISE, (const unsigned char*)(noise + (size_t)row0 * 32), t);
    cppad<128, 8, 192>(sb + SM_BUF, gW1, t);
    CPCOMMIT();
    cppad<128, 8, 192>(sb + SM_BUF + SM_BUFS, gW1 + 16384, t);
    CPCOMMIT();

    const float* xrow = x + (size_t)(row0 + w * 16 + g) * 512;
    float2 xfA[8], xfB[8];
    loadx(xrow, 0, xfA, q);

    float acc[16][4];
    #pragma unroll
    for (int j = 0; j < 16; j++) { acc[j][0]=0.f; acc[j][1]=0.f; acc[j][2]=0.f; acc[j][3]=0.f; }

    // ============== GEMM1: z1[64x128] = x @ W1^T, 16 chunks of 32 k ==============
    for (int c = 0; c < 16; c += 2) {
        loadx(xrow, c + 1, xfB, q);
        CPWAIT1(); __syncthreads();
        compute_chunk1(smc, SM_BUF, xfA, g, q, acc);
        __syncthreads();
        if (c + 2 < 16) { cppad<128, 8, 192>(sb + SM_BUF, gW1 + (size_t)(c + 2) * 16384, t); CPCOMMIT(); }
        if (c + 2 < 16) loadx(xrow, c + 2, xfA, q);
        if (c == 14) { CPWAIT0(); } else { CPWAIT1(); }
        __syncthreads();
        compute_chunk1(smc, SM_BUF + SM_BUFS, xfB, g, q, acc);
        __syncthreads();
        if (c + 3 < 16) { cppad<128, 8, 192>(sb + SM_BUF + SM_BUFS, gW1 + (size_t)(c + 3) * 16384, t); CPCOMMIT(); }
    }

    // kick off W4 chunk 0/1 copies — overlap with GEMM2/3 and epilogues
    cppad<32, 32, 576>(sb + SM_BUF, gW4, t);
    CPCOMMIT();
    cppad<32, 32, 576>(sb + SM_BUF + SM_BUFS, gW4 + 32 * 512, t);
    CPCOMMIT();

    // ---- epilogue 1: +b1, relu, split -> chained A fragments (8 kb) ----
    uint32_t ah[8][4], al[8][4];
    #pragma unroll
    for (int j = 0; j < 16; j++) {
        float bb0 = bias[j * 8 + q * 2], bb1 = bias[j * 8 + q * 2 + 1];
        float v0 = fmaxf(acc[j][0] + bb0, 0.f), v1 = fmaxf(acc[j][1] + bb1, 0.f);
        float v2 = fmaxf(acc[j][2] + bb0, 0.f), v3 = fmaxf(acc[j][3] + bb1, 0.f);
        uint32_t h01, l01, h23, l23;
        split2(v0, v1, h01, l01);
        split2(v2, v3, h23, l23);
        int kb = j >> 1, s = (j & 1) * 2;
        ah[kb][s] = h01; ah[kb][s + 1] = h23;
        al[kb][s] = l01; al[kb][s + 1] = l23;
    }

    // ============== GEMM2: z2[64x32] = z1 @ W2^T (K=128) ==============
    float acc2[4][4];
    #pragma unroll
    for (int j = 0; j < 4; j++) { acc2[j][0]=0.f; acc2[j][1]=0.f; acc2[j][2]=0.f; acc2[j][3]=0.f; }
    #pragma unroll
    for (int kb = 0; kb < 8; kb++)
        gemm_step_r<4, 576>(smc, ah[kb], al[kb], SM_W2 + kb * 64, g, q, acc2);

    // ---- epilogue 2: +b2, power-normalize, rotate by h, +noise (noise from smem) ----
    uint32_t a3h[2][4], a3l[2][4];
    {
        float vv[4][4];
        float ssg = 0.f, ssh = 0.f;
        #pragma unroll
        for (int j = 0; j < 4; j++) {
            float bb0 = bias[128 + j * 8 + q * 2], bb1 = bias[128 + j * 8 + q * 2 + 1];
            vv[j][0] = acc2[j][0] + bb0; vv[j][1] = acc2[j][1] + bb1;
            vv[j][2] = acc2[j][2] + bb0; vv[j][3] = acc2[j][3] + bb1;
            ssg += vv[j][0] * vv[j][0] + vv[j][1] * vv[j][1];
            ssh += vv[j][2] * vv[j][2] + vv[j][3] * vv[j][3];
        }
        ssg += __shfl_xor_sync(0xffffffffu, ssg, 1);
        ssg += __shfl_xor_sync(0xffffffffu, ssg, 2);
        ssh += __shfl_xor_sync(0xffffffffu, ssh, 1);
        ssh += __shfl_xor_sync(0xffffffffu, ssh, 2);
        float scg = 4.0f / sqrtf(ssg);       // sqrt(N*0.5) = 4
        float sch = 4.0f / sqrtf(ssh);
        float hc = __ldg(hch), hs = __ldg(hch + 1);
        const char* np = smc + SM_NOISE;
        int r = 16 * w + g;
        #pragma unroll
        for (int j = 0; j < 4; j++) {
            int c0 = j * 8 + q * 2;
            float2 ng = *(const float2*)(np + (size_t)r * 144 + c0 * 4);
            float2 nh = *(const float2*)(np + (size_t)(r + 8) * 144 + c0 * 4);
            float y0 = scg * (vv[j][0] * hc - vv[j][1] * hs) + ng.x;
            float y1 = scg * (vv[j][0] * hs + vv[j][1] * hc) + ng.y;
            float y2 = sch * (vv[j][2] * hc - vv[j][3] * hs) + nh.x;
            float y3 = sch * (vv[j][2] * hs + vv[j][3] * hc) + nh.y;
            uint32_t h01, l01, h23, l23;
            split2(y0, y1, h01, l01);
            split2(y2, y3, h23, l23);
            int kb = j >> 1, s = (j & 1) * 2;
            a3h[kb][s] = h01; a3h[kb][s + 1] = h23;
            a3l[kb][s] = l01; a3l[kb][s + 1] = l23;
        }
    }

    // ============== GEMM3: d[64x128] = y @ W3^T (K=32) ==============
    #pragma unroll
    for (int j = 0; j < 16; j++) { acc[j][0]=0.f; acc[j][1]=0.f; acc[j][2]=0.f; acc[j][3]=0.f; }
    #pragma unroll
    for (int kb = 0; kb < 2; kb++)
        gemm_step_r<16, 192>(smc, a3h[kb], a3l[kb], SM_W3 + kb * 64, g, q, acc);

    // ---- epilogue 3: +b3, relu, split -> A4 fragments ----
    #pragma unroll
    for (int j = 0; j < 16; j++) {
        float bb0 = bias[160 + j * 8 + q * 2], bb1 = bias[160 + j * 8 + q * 2 + 1];
        float v0 = fmaxf(acc[j][0] + bb0, 0.f), v1 = fmaxf(acc[j][1] + bb1, 0.f);
        float v2 = fmaxf(acc[j][2] + bb0, 0.f), v3 = fmaxf(acc[j][3] + bb1, 0.f);
        uint32_t h01, l01, h23, l23;
        split2(v0, v1, h01, l01);
        split2(v2, v3, h23, l23);
        int kb = j >> 1, s = (j & 1) * 2;
        ah[kb][s] = h01; ah[kb][s + 1] = h23;
        al[kb][s] = l01; al[kb][s + 1] = l23;
    }

    // ============== GEMM4: out[64x512] = d @ W4^T, 16 n-chunks of 32 ==============
    for (int nc = 0; nc < 16; nc++) {
        if (nc == 15) { CPWAIT0(); } else { CPWAIT1(); }
        __syncthreads();
        int buf = SM_BUF + (nc & 1) * SM_BUFS;
        float acc4[4][4];
        #pragma unroll
        for (int j = 0; j < 4; j++) { acc4[j][0]=0.f; acc4[j][1]=0.f; acc4[j][2]=0.f; acc4[j][3]=0.f; }
        #pragma unroll
        for (int kb = 0; kb < 8; kb++)
            gemm_step_r<4, 576>(smc, ah[kb], al[kb], buf + kb * 64, g, q, acc4);
        __syncthreads();
        if (nc + 2 < 16) {
            cppad<32, 32, 576>(sb + buf, gW4 + (size_t)(nc + 2) * 32 * 512, t);
            CPCOMMIT();
        }
        // epilogue 4: +b4, store fp32
        #pragma unroll
        for (int j = 0; j < 4; j++) {
            int col = nc * 32 + j * 8 + q * 2;
            float bb0 = bias[288 + col], bb1 = bias[288 + col + 1];
            int r = row0 + 16 * w + g;
            *(float2*)(out + (size_t)r * 512 + col) =
                make_float2(acc4[j][0] + bb0, acc4[j][1] + bb1);
            *(float2*)(out + (size_t)(r + 8) * 512 + col) =
                make_float2(acc4[j][2] + bb0, acc4[j][3] + bb1);
        }
    }
}

extern "C" void kernel_launch(void* const* d_in, const int* in_sizes, int n_in,
                              void* d_out, int out_size) {
    const float* x     = (const float*)d_in[0];
    const float* noise = (const float*)d_in[1];
    const float* hch   = (const float*)d_in[2];
    const float* W1    = (const float*)d_in[3];
    const float* b1    = (const float*)d_in[4];
    const float* W2    = (const float*)d_in[5];
    const float* b2    = (const float*)d_in[6];
    const float* W3    = (const float*)d_in[7];
    const float* b3    = (const float*)d_in[8];
    const float* W4    = (const float*)d_in[9];
    const float* b4    = (const float*)d_in[10];
    float* out = (float*)d_out;

    static int configured = 0;
    if (!configured) {
        cudaFuncSetAttribute(channel_net_kernel,
                             cudaFuncAttributeMaxDynamicSharedMemorySize, SM_TOTAL);
        configured = 1;
    }
    setup_kernel<<<136, 256>>>(W1, W2, W3, W4);
    channel_net_kernel<<<2048, 128, SM_TOTAL>>>(
        x, noise, hch, b1, b2, b3, b4, out);
}